// round 5
// baseline (speedup 1.0000x reference)
#include <cuda_runtime.h>

// Problem constants (fixed dataset):
//   x      [2, 200000, 32]  fp32
//   pos    [2, 200000, 3]   fp32  (uniform [0,1))
//   kernel [3,3,3,32,32]    fp32  (o-major: [o][ci][co], o = oi*9+oj*3+ok)
//   bias   [32]             fp32
//   out    [2, 32, 66,66,66] fp32
#define NPART   400000
#define NPERB   200000
#define DD      66
#define HWP     4356        // 66*66
#define DHW     287496      // 66*66*66
#define NCOLS   8192        // 2 batches * 64*64 input columns
#define NOUTC   8712        // 2 * 66*66 output columns

// Sort state (all static __device__ — no allocation).
__device__ int   g_hist[NCOLS];          // zero at load; re-zeroed by tail kernel
__device__ int   g_off[NCOLS + 1];
__device__ int   g_cursor[NCOLS];
__device__ float g_tmp[(size_t)NPART * 12];   // unsorted payload
__device__ float g_pay[(size_t)NPART * 12];   // column-sorted payload

// ---------------------------------------------------------------------------
// Pass 1: per-particle weights + column id, histogram.
// Payload layout (12 floats): {wx0,wx1,wx2, wy0 | wy1,wy2,wz0,wz1 | wz2, bz0(int), pid(int), col(int)}
// ---------------------------------------------------------------------------
__global__ void prep_kernel(const float* __restrict__ pos) {
    const int pid = blockIdx.x * blockDim.x + threadIdx.x;
    if (pid >= NPART) return;
    const float px = pos[pid * 3 + 0] * 64.f;
    const float py = pos[pid * 3 + 1] * 64.f;
    const float pz = pos[pid * 3 + 2] * 64.f;
    const int bx = (int)px, by = (int)py, bz = (int)pz;
    const float fx = px - (float)bx - 0.5f;
    const float fy = py - (float)by - 0.5f;
    const float fz = pz - (float)bz - 0.5f;
    const int b = (pid >= NPERB) ? 1 : 0;
    const int col = b * 4096 + bx * 64 + by;
    atomicAdd(&g_hist[col], 1);

    float4 A, B4, C4;
    A.x = 0.5f * (0.5f - fx) * (0.5f - fx);
    A.y = 0.75f - fx * fx;
    A.z = 0.5f * (0.5f + fx) * (0.5f + fx);
    A.w = 0.5f * (0.5f - fy) * (0.5f - fy);
    B4.x = 0.75f - fy * fy;
    B4.y = 0.5f * (0.5f + fy) * (0.5f + fy);
    B4.z = 0.5f * (0.5f - fz) * (0.5f - fz);
    B4.w = 0.75f - fz * fz;
    C4.x = 0.5f * (0.5f + fz) * (0.5f + fz);
    C4.y = __int_as_float(bz);
    C4.z = __int_as_float(pid);
    C4.w = __int_as_float(col);
    float4* t = reinterpret_cast<float4*>(g_tmp + (size_t)pid * 12);
    t[0] = A; t[1] = B4; t[2] = C4;
}

// ---------------------------------------------------------------------------
// Pass 2: exclusive scan of 8192 counts (one block, 1024 threads x 8 each).
// ---------------------------------------------------------------------------
__global__ void scan_kernel() {
    __shared__ int wsum[32];
    const int t = threadIdx.x;
    int v[8];
    int run = 0;
#pragma unroll
    for (int k = 0; k < 8; ++k) {
        const int c = g_hist[t * 8 + k];
        v[k] = run; run += c;
    }
    const int lane = t & 31, wi = t >> 5;
    int inc = run;
#pragma unroll
    for (int d = 1; d < 32; d <<= 1) {
        const int n = __shfl_up_sync(0xffffffffu, inc, d);
        if (lane >= d) inc += n;
    }
    if (lane == 31) wsum[wi] = inc;
    __syncthreads();
    if (wi == 0) {
        int wv = wsum[lane];
#pragma unroll
        for (int d = 1; d < 32; d <<= 1) {
            const int n = __shfl_up_sync(0xffffffffu, wv, d);
            if (lane >= d) wv += n;
        }
        wsum[lane] = wv;
    }
    __syncthreads();
    const int wexcl = (wi == 0) ? 0 : wsum[wi - 1];
    const int excl = wexcl + inc - run;
#pragma unroll
    for (int k = 0; k < 8; ++k) {
        const int o = excl + v[k];
        g_off[t * 8 + k] = o;
        g_cursor[t * 8 + k] = o;
    }
    if (t == 1023) g_off[NCOLS] = wexcl + inc;   // = NPART
}

// ---------------------------------------------------------------------------
// Pass 3: scatter payloads into column-sorted order.
// ---------------------------------------------------------------------------
__global__ void scatter_idx_kernel() {
    const int pid = blockIdx.x * blockDim.x + threadIdx.x;
    if (pid >= NPART) return;
    const float4* t = reinterpret_cast<const float4*>(g_tmp + (size_t)pid * 12);
    const float4 A = t[0], B4 = t[1], C4 = t[2];
    const int col = __float_as_int(C4.w);
    const int p = atomicAdd(&g_cursor[col], 1);
    float4* d = reinterpret_cast<float4*>(g_pay + (size_t)p * 12);
    d[0] = A; d[1] = B4; d[2] = C4;
}

// ---------------------------------------------------------------------------
// Pass 4 (main): one WARP per output z-column (b, nx, ny).
// Gathers particles from the <=9 input columns (bx=nx-dx, by=ny-dy); each
// particle contributes its (oi=dx, oj=dy, ok=0..2) taps. Lane c owns channel
// c. Column strip [66 z][33 pad] accumulated in smem with plain LDS/FADD/STS
// (single-owner => NO atomics anywhere). Direct coalesced STG to out.
// ---------------------------------------------------------------------------
__global__ __launch_bounds__(128) void main_kernel(
    const float* __restrict__ x,
    const float* __restrict__ kern,
    const float* __restrict__ bias,
    float* __restrict__ out)
{
    __shared__ float strip_s[4][DD * 33];     // 34.8 KB
    const int wid  = threadIdx.x >> 5;
    const int lane = threadIdx.x & 31;
    const int colid = blockIdx.x * 4 + wid;   // 2178*4 = 8712 exact
    const int b  = colid / HWP;
    const int r  = colid % HWP;
    const int nx = r / DD;
    const int ny = r % DD;

    float* const strip = &strip_s[wid][0];
    for (int i = lane; i < DD * 33; i += 32) strip[i] = 0.f;
    __syncwarp();

    const float bc = bias[lane];

    for (int dx = 0; dx < 3; ++dx) {
        const int bx = nx - dx;
        if (bx < 0 || bx > 63) continue;
        for (int dy = 0; dy < 3; ++dy) {
            const int by = ny - dy;
            if (by < 0 || by > 63) continue;
            const int col = b * 4096 + bx * 64 + by;
            const int s0 = g_off[col];
            const int s1 = g_off[col + 1];
            if (s0 == s1) continue;

            // K[3 ok][16 ci-pairs] for this (oi=dx, oj=dy), lane's channel.
            unsigned long long kk[3][16];
#pragma unroll
            for (int ok = 0; ok < 3; ++ok) {
                const float* kb = kern + ((dx * 9 + dy * 3 + ok) << 10) + lane;
#pragma unroll
                for (int t = 0; t < 16; ++t) {
                    const float ke = kb[64 * t];
                    const float ko = kb[64 * t + 32];
                    asm("mov.b64 %0, {%1, %2};" : "=l"(kk[ok][t]) : "f"(ke), "f"(ko));
                }
            }

            for (int i = s0; i < s1; ++i) {
                const float4* pp =
                    reinterpret_cast<const float4*>(g_pay + (size_t)i * 12);
                const float4 A  = pp[0];
                const float4 B4 = pp[1];
                const float4 C4 = pp[2];
                const int bz0 = __float_as_int(C4.y);
                const int pid = __float_as_int(C4.z);

                const float wxv = (dx == 0) ? A.x : ((dx == 1) ? A.y : A.z);
                const float wyv = (dy == 0) ? A.w : ((dy == 1) ? B4.x : B4.y);
                const float wij = wxv * wyv;

                const ulonglong2* xq =
                    reinterpret_cast<const ulonglong2*>(x + (size_t)pid * 32);
                unsigned long long y0a = 0ull, y0b = 0ull, y1a = 0ull,
                                   y1b = 0ull, y2a = 0ull, y2b = 0ull;
#pragma unroll
                for (int t = 0; t < 8; ++t) {
                    const ulonglong2 xv = xq[t];            // broadcast LDG.128
                    asm("fma.rn.f32x2 %0, %1, %2, %0;" : "+l"(y0a) : "l"(xv.x), "l"(kk[0][2 * t]));
                    asm("fma.rn.f32x2 %0, %1, %2, %0;" : "+l"(y0b) : "l"(xv.y), "l"(kk[0][2 * t + 1]));
                    asm("fma.rn.f32x2 %0, %1, %2, %0;" : "+l"(y1a) : "l"(xv.x), "l"(kk[1][2 * t]));
                    asm("fma.rn.f32x2 %0, %1, %2, %0;" : "+l"(y1b) : "l"(xv.y), "l"(kk[1][2 * t + 1]));
                    asm("fma.rn.f32x2 %0, %1, %2, %0;" : "+l"(y2a) : "l"(xv.x), "l"(kk[2][2 * t]));
                    asm("fma.rn.f32x2 %0, %1, %2, %0;" : "+l"(y2b) : "l"(xv.y), "l"(kk[2][2 * t + 1]));
                }
                float lo, hi, l2, h2;
                unsigned long long s;
                asm("add.rn.f32x2 %0, %1, %2;" : "=l"(s) : "l"(y0a), "l"(y0b));
                asm("mov.b64 {%0, %1}, %2;" : "=f"(lo), "=f"(hi) : "l"(s));
                const float d0 = lo + hi + bc;
                asm("add.rn.f32x2 %0, %1, %2;" : "=l"(s) : "l"(y1a), "l"(y1b));
                asm("mov.b64 {%0, %1}, %2;" : "=f"(l2), "=f"(h2) : "l"(s));
                const float d1 = l2 + h2 + bc;
                asm("add.rn.f32x2 %0, %1, %2;" : "=l"(s) : "l"(y2a), "l"(y2b));
                asm("mov.b64 {%0, %1}, %2;" : "=f"(lo), "=f"(hi) : "l"(s));
                const float d2 = lo + hi + bc;

                float* sp = strip + bz0 * 33 + lane;
                sp[0]      += (wij * B4.z) * d0;    // ok=0  (single owner: no atomics)
                sp[33]     += (wij * B4.w) * d1;    // ok=1
                sp[66]     += (wij * C4.x) * d2;    // ok=2
            }
        }
    }
    __syncwarp();

    // Writeback: out[(b*32+c)*DHW + nx*HWP + ny*DD + z], coalesced over z.
    float* const ob = out + (size_t)(b * 32) * DHW + nx * HWP + ny * DD;
#pragma unroll 4
    for (int c = 0; c < 32; ++c) {
        float* oc = ob + (size_t)c * DHW;
#pragma unroll
        for (int zq = 0; zq < 3; ++zq) {
            const int z = zq * 32 + lane;
            if (z < DD) oc[z] = strip[z * 33 + c];   // conflict-free LDS
        }
    }
}

// ---------------------------------------------------------------------------
// Tail: re-zero histogram for the next call (zero at module load too).
// ---------------------------------------------------------------------------
__global__ void zero_hist_kernel() {
    const int i = blockIdx.x * blockDim.x + threadIdx.x;
    if (i < NCOLS) g_hist[i] = 0;
}

// ---------------------------------------------------------------------------
extern "C" void kernel_launch(void* const* d_in, const int* in_sizes, int n_in,
                              void* d_out, int out_size)
{
    const float* x    = reinterpret_cast<const float*>(d_in[0]);
    const float* pos  = reinterpret_cast<const float*>(d_in[1]);
    const float* kern = reinterpret_cast<const float*>(d_in[2]);
    const float* bias = reinterpret_cast<const float*>(d_in[3]);
    float* out = reinterpret_cast<float*>(d_out);

    prep_kernel<<<(NPART + 255) / 256, 256>>>(pos);
    scan_kernel<<<1, 1024>>>();
    scatter_idx_kernel<<<(NPART + 255) / 256, 256>>>();
    main_kernel<<<NOUTC / 4, 128>>>(x, kern, bias, out);
    zero_hist_kernel<<<8, 1024>>>();
}

// round 7
// speedup vs baseline: 3.5163x; 3.5163x over previous
#include <cuda_runtime.h>
#include <cstdint>

// Problem: x[2,200000,32] f32, pos[2,200000,3] f32, kernel[3,3,3,32,32] f32,
// bias[32] f32 -> out[2,32,66,66,66] f32.
#define NPART 400000
#define NPERB 200000
#define DD    66
#define HWP   4356
#define DHW   287496

// Channel-last scratch [2*DHW][32]; zero at module load, re-zeroed at end of
// every launch.
__device__ float g_scratch[(size_t)2 * DHW * 32];          // 73.6 MB

// Pre-split kernel matrices, B[n=co][k=ci] per tap: hi and lo bf16.
__device__ __align__(16) unsigned short g_Bh[27][32][32];
__device__ __align__(16) unsigned short g_Bl[27][32][32];

// ---------------- helpers --------------------------------------------------
__device__ __forceinline__ unsigned short f2bf(float f) {
    unsigned short u; asm("cvt.rn.bf16.f32 %0, %1;" : "=h"(u) : "f"(f)); return u;
}
__device__ __forceinline__ float bf2f(unsigned short u) {
    return __uint_as_float(((uint32_t)u) << 16);
}
__device__ __forceinline__ uint32_t smem_u32(const void* p) {
    uint32_t a;
    asm("{ .reg .u64 t; cvta.to.shared.u64 t, %1; cvt.u32.u64 %0, t; }"
        : "=r"(a) : "l"(p));
    return a;
}
__device__ __forceinline__ void ldm4(uint32_t* r, uint32_t addr) {
    asm volatile("ldmatrix.sync.aligned.m8n8.x4.shared.b16 {%0,%1,%2,%3}, [%4];"
                 : "=r"(r[0]), "=r"(r[1]), "=r"(r[2]), "=r"(r[3]) : "r"(addr));
}
__device__ __forceinline__ void mma_bf16(float* d, const uint32_t* a,
                                         uint32_t b0, uint32_t b1) {
    asm volatile(
        "mma.sync.aligned.m16n8k16.row.col.f32.bf16.bf16.f32 "
        "{%0,%1,%2,%3}, {%4,%5,%6,%7}, {%8,%9}, {%0,%1,%2,%3};"
        : "+f"(d[0]), "+f"(d[1]), "+f"(d[2]), "+f"(d[3])
        : "r"(a[0]), "r"(a[1]), "r"(a[2]), "r"(a[3]), "r"(b0), "r"(b1));
}

// ---------------------------------------------------------------------------
// Prebuild: split kernel into bf16 hi/lo, transposed to B[n=co][k=ci].
// ---------------------------------------------------------------------------
__global__ void prebuild_kernel(const float* __restrict__ kern) {
    const int g = blockIdx.x;                 // 27
    for (int idx = threadIdx.x; idx < 1024; idx += 256) {
        const int co = idx >> 5, ci = idx & 31;
        const float f = kern[(size_t)g * 1024 + ci * 32 + co];
        const unsigned short hi = f2bf(f);
        g_Bh[g][co][ci] = hi;
        g_Bl[g][co][ci] = f2bf(f - bf2f(hi));
    }
}

// ---------------------------------------------------------------------------
// Main kernel: CTA = 128 threads = 4 warps, each warp owns 32 particles.
// Per (oi,oj,ok): D[32p,32co] = X[32,32] @ K^T via 6 mma (2m x 4n... per term
// 16 mma, 3 split terms = 48). Epilogue: (d+bias)*w3 on fragments -> pb smem
// [p][co] -> 8 coalesced float4 REDs into g_scratch.
// ---------------------------------------------------------------------------
#define OFF_AH 0
#define OFF_AL 10240
#define OFF_BH 20480
#define OFF_BL 28160
#define OFF_WX 35840
#define OFF_WY 37376
#define OFF_WZ 38912
#define OFF_NB 40448
#define OFF_PB 40960
#define SMEM_BYTES (OFF_PB + 4 * 32 * 36 * 4)   // 59392

__global__ __launch_bounds__(128) void main_kernel(
    const float* __restrict__ x,
    const float* __restrict__ pos,
    const float* __restrict__ bias)
{
    extern __shared__ __align__(16) char smem[];
    const int tid  = threadIdx.x;
    const int w    = tid >> 5;
    const int lane = tid & 31;
    const int gid  = lane >> 2;          // fragment group id (row)
    const int tig  = lane & 3;           // thread-in-group (col pair)
    const int pid  = blockIdx.x * 128 + w * 32 + lane;
    const uint32_t sb = smem_u32(smem);

    // ---- stage A: x -> bf16 hi/lo rows (80B stride, conflict-free) ----
    {
        float xv[32];
        const float4* xp = reinterpret_cast<const float4*>(x + (size_t)pid * 32);
#pragma unroll
        for (int t = 0; t < 8; ++t) {
            const float4 v = xp[t];
            xv[4 * t] = v.x; xv[4 * t + 1] = v.y; xv[4 * t + 2] = v.z; xv[4 * t + 3] = v.w;
        }
        uint32_t hw[16], lw[16];
#pragma unroll
        for (int k = 0; k < 16; ++k) {
            const float f0 = xv[2 * k], f1 = xv[2 * k + 1];
            const unsigned short h0 = f2bf(f0), h1 = f2bf(f1);
            const unsigned short l0 = f2bf(f0 - bf2f(h0)), l1 = f2bf(f1 - bf2f(h1));
            hw[k] = (uint32_t)h0 | ((uint32_t)h1 << 16);
            lw[k] = (uint32_t)l0 | ((uint32_t)l1 << 16);
        }
        char* rH = smem + OFF_AH + (w * 32 + lane) * 80;
        char* rL = smem + OFF_AL + (w * 32 + lane) * 80;
#pragma unroll
        for (int c = 0; c < 4; ++c) {
            reinterpret_cast<uint4*>(rH)[c] = make_uint4(hw[4*c], hw[4*c+1], hw[4*c+2], hw[4*c+3]);
            reinterpret_cast<uint4*>(rL)[c] = make_uint4(lw[4*c], lw[4*c+1], lw[4*c+2], lw[4*c+3]);
        }
    }

    // ---- weights + node for own particle ----
    {
        const float px = pos[pid * 3 + 0] * 64.f;
        const float py = pos[pid * 3 + 1] * 64.f;
        const float pz = pos[pid * 3 + 2] * 64.f;
        const int bx = (int)px, by = (int)py, bz = (int)pz;
        const float fx = px - (float)bx - 0.5f;
        const float fy = py - (float)by - 0.5f;
        const float fz = pz - (float)bz - 0.5f;
        float* WX = reinterpret_cast<float*>(smem + OFF_WX) + w * 96;
        float* WY = reinterpret_cast<float*>(smem + OFF_WY) + w * 96;
        float* WZ = reinterpret_cast<float*>(smem + OFF_WZ) + w * 96;
        WX[lane]      = 0.5f * (0.5f - fx) * (0.5f - fx);
        WX[32 + lane] = 0.75f - fx * fx;
        WX[64 + lane] = 0.5f * (0.5f + fx) * (0.5f + fx);
        WY[lane]      = 0.5f * (0.5f - fy) * (0.5f - fy);
        WY[32 + lane] = 0.75f - fy * fy;
        WY[64 + lane] = 0.5f * (0.5f + fy) * (0.5f + fy);
        WZ[lane]      = 0.5f * (0.5f - fz) * (0.5f - fz);
        WZ[32 + lane] = 0.75f - fz * fz;
        WZ[64 + lane] = 0.5f * (0.5f + fz) * (0.5f + fz);
        const int b = (pid >= NPERB) ? 1 : 0;
        reinterpret_cast<int*>(smem + OFF_NB)[w * 32 + lane] =
            b * DHW + bx * HWP + by * DD + bz;
    }
    __syncthreads();

    // ---- per-lane constants ----
    float bias_r[4][2];
#pragma unroll
    for (int nb = 0; nb < 4; ++nb) {
        bias_r[nb][0] = bias[nb * 8 + 2 * tig];
        bias_r[nb][1] = bias[nb * 8 + 2 * tig + 1];
    }

    // ---- A fragments (persistent registers) ----
    uint32_t aH[2][2][4], aL[2][2][4];
#pragma unroll
    for (int mb = 0; mb < 2; ++mb)
#pragma unroll
        for (int ks = 0; ks < 2; ++ks) {
            const uint32_t off = (uint32_t)((w * 32 + mb * 16 + (lane & 15)) * 80
                                            + ks * 32 + (lane >> 4) * 16);
            ldm4(aH[mb][ks], sb + OFF_AH + off);
            ldm4(aL[mb][ks], sb + OFF_AL + off);
        }

    const float* WX = reinterpret_cast<float*>(smem + OFF_WX) + w * 96;
    const float* WY = reinterpret_cast<float*>(smem + OFF_WY) + w * 96;
    const float* WZ = reinterpret_cast<float*>(smem + OFF_WZ) + w * 96;
    const int*   NBw = reinterpret_cast<int*>(smem + OFF_NB) + w * 32;
    float* const pbw = reinterpret_cast<float*>(smem + OFF_PB) + w * 1152;  // 32*36

    for (int g = 0; g < 9; ++g) {
        const int oi = g / 3, oj = g % 3;

        // ---- stage B hi/lo for this group's 3 ok taps ----
        __syncthreads();
#pragma unroll
        for (int it = 0; it < 3; ++it) {
            const int idx = it * 128 + tid;          // 384 chunks per side
            const int okk = idx >> 7, r = idx & 127;
            const int co = r >> 2, ch = r & 3;
            const uint4* sh = reinterpret_cast<const uint4*>(&g_Bh[g * 3 + okk][co][0]);
            const uint4* sl = reinterpret_cast<const uint4*>(&g_Bl[g * 3 + okk][co][0]);
            reinterpret_cast<uint4*>(smem + OFF_BH + okk * 2560 + co * 80)[ch] = sh[ch];
            reinterpret_cast<uint4*>(smem + OFF_BL + okk * 2560 + co * 80)[ch] = sl[ch];
        }
        __syncthreads();

        float w12[4];
#pragma unroll
        for (int i = 0; i < 4; ++i) {
            const int p = gid + i * 8;
            w12[i] = WX[oi * 32 + p] * WY[oj * 32 + p];
        }

        for (int ok = 0; ok < 3; ++ok) {
            // ---- B fragments ----
            uint32_t bh[4][4], bl[4][4];
#pragma unroll
            for (int nb = 0; nb < 4; ++nb) {
                const uint32_t ba = sb + OFF_BH + (uint32_t)(ok * 2560
                                    + (nb * 8 + (lane & 7)) * 80 + (lane >> 3) * 16);
                ldm4(bh[nb], ba);
                ldm4(bl[nb], ba + (OFF_BL - OFF_BH));
            }

            // ---- 3-term split MMA ----
            float d[2][4][4];
#pragma unroll
            for (int mb = 0; mb < 2; ++mb)
#pragma unroll
                for (int nb = 0; nb < 4; ++nb) {
#pragma unroll
                    for (int q = 0; q < 4; ++q) d[mb][nb][q] = 0.f;
                    mma_bf16(d[mb][nb], aH[mb][0], bh[nb][0], bh[nb][1]);
                    mma_bf16(d[mb][nb], aH[mb][1], bh[nb][2], bh[nb][3]);
                    mma_bf16(d[mb][nb], aH[mb][0], bl[nb][0], bl[nb][1]);
                    mma_bf16(d[mb][nb], aH[mb][1], bl[nb][2], bl[nb][3]);
                    mma_bf16(d[mb][nb], aL[mb][0], bh[nb][0], bh[nb][1]);
                    mma_bf16(d[mb][nb], aL[mb][1], bh[nb][2], bh[nb][3]);
                }

            float w3[4];
#pragma unroll
            for (int i = 0; i < 4; ++i)
                w3[i] = w12[i] * WZ[ok * 32 + gid + i * 8];

            // ---- weighted fragments -> pb [p][co] ----
#pragma unroll
            for (int mb = 0; mb < 2; ++mb)
#pragma unroll
                for (int nb = 0; nb < 4; ++nb) {
                    const int r0 = mb * 16 + gid;
                    const int c  = nb * 8 + 2 * tig;
                    float2 v0, v1;
                    v0.x = (d[mb][nb][0] + bias_r[nb][0]) * w3[mb * 2];
                    v0.y = (d[mb][nb][1] + bias_r[nb][1]) * w3[mb * 2];
                    v1.x = (d[mb][nb][2] + bias_r[nb][0]) * w3[mb * 2 + 1];
                    v1.y = (d[mb][nb][3] + bias_r[nb][1]) * w3[mb * 2 + 1];
                    *reinterpret_cast<float2*>(&pbw[r0 * 36 + c])      = v0;
                    *reinterpret_cast<float2*>(&pbw[(r0 + 8) * 36 + c]) = v1;
                }
            __syncwarp();

            // ---- coalesced float4 REDs into channel-last scratch ----
            const int obase = oi * HWP + oj * DD + ok;
#pragma unroll
            for (int i = 0; i < 8; ++i) {
                const int f = i * 32 + lane;
                const int p = f >> 3, q = f & 7;
                const int nd = NBw[p] + obase;
                const float4 v = *reinterpret_cast<const float4*>(&pbw[p * 36 + q * 4]);
                atomicAdd(reinterpret_cast<float4*>(
                              g_scratch + (size_t)nd * 32 + q * 4), v);
            }
            __syncwarp();
        }
    }
}

// ---------------------------------------------------------------------------
// Transpose scratch [b][node][c] -> out [b][c][node]  (R3-proven).
// ---------------------------------------------------------------------------
__global__ void transpose_kernel(float* __restrict__ out) {
    __shared__ float t[32][33];
    const int nd0 = blockIdx.x * 32;
    const int b   = blockIdx.y;
    const int tx  = threadIdx.x, ty = threadIdx.y;
#pragma unroll
    for (int k = 0; k < 4; ++k) {
        const int nd = nd0 + ty + k * 8;
        if (nd < DHW)
            t[ty + k * 8][tx] = g_scratch[((size_t)b * DHW + nd) * 32 + tx];
    }
    __syncthreads();
    const int nd = nd0 + tx;
    if (nd < DHW) {
#pragma unroll
        for (int k = 0; k < 4; ++k) {
            const int c = ty + k * 8;
            out[((size_t)b * 32 + c) * DHW + nd] = t[tx][c];
        }
    }
}

__global__ void zero_scratch_kernel() {
    const size_t n4 = (size_t)2 * DHW * 32 / 4;
    float4* p = reinterpret_cast<float4*>(g_scratch);
    for (size_t i = (size_t)blockIdx.x * blockDim.x + threadIdx.x;
         i < n4; i += (size_t)gridDim.x * blockDim.x)
        p[i] = make_float4(0.f, 0.f, 0.f, 0.f);
}

// ---------------------------------------------------------------------------
extern "C" void kernel_launch(void* const* d_in, const int* in_sizes, int n_in,
                              void* d_out, int out_size)
{
    const float* x    = reinterpret_cast<const float*>(d_in[0]);
    const float* pos  = reinterpret_cast<const float*>(d_in[1]);
    const float* kern = reinterpret_cast<const float*>(d_in[2]);
    const float* bias = reinterpret_cast<const float*>(d_in[3]);
    float* out = reinterpret_cast<float*>(d_out);

    static int attr_done = 0;
    if (!attr_done) {
        cudaFuncSetAttribute(main_kernel,
                             cudaFuncAttributeMaxDynamicSharedMemorySize,
                             SMEM_BYTES);
        attr_done = 1;
    }

    prebuild_kernel<<<27, 256>>>(kern);
    main_kernel<<<NPART / 128, 128, SMEM_BYTES>>>(x, pos, bias);
    transpose_kernel<<<dim3((DHW + 31) / 32, 2), dim3(32, 8)>>>(out);
    zero_scratch_kernel<<<4096, 256>>>();
}